// round 7
// baseline (speedup 1.0000x reference)
#include <cuda_runtime.h>
#include <math.h>

// ---- problem dims ----
#define BN 128
#define CC 512
#define HW 196
#define KF 2
#define AA 2000
#define TT 20
#define EE 300
#define LH 1024
#define MH 512
#define G4 4096   // 4*LH

// ---- scratch (device globals; no runtime allocation) ----
__device__ float g_maps[BN * HW];
__device__ float g_denom[BN];
__device__ float g_hmeas[BN * MH];
__device__ float g_att[BN * CC];
__device__ float g_root[BN * AA];               // logits -> softmax probs (in place)
__device__ float g_X[(size_t)BN * TT * G4];     // emb@Wx + b_lstm, precomputed
__device__ float g_h[2][BN * LH];               // double-buffered hidden state
__device__ float g_c[BN * LH];                  // in-place (unique owner per (b,j))
__device__ float g_hlast[BN * LH];
__device__ float g_enc[BN * AA];

// ---- zero h0 / c0 ----
__global__ void zero_kernel() {
    int i = blockIdx.x * blockDim.x + threadIdx.x;
    if (i < BN * LH) { g_h[0][i] = 0.f; g_c[i] = 0.f; }
}

// ---- Find: maps[b,hw] = relu(w0.f) * relu(w1.f); denom[b] = sum + 1e-6 ----
__global__ void find_kernel(const float* __restrict__ feat,
                            const int* __restrict__ find_inst,
                            const float* __restrict__ W_find) {
    int b = blockIdx.x;
    __shared__ float w0[CC], w1[CC];
    __shared__ float red[256];
    int i0 = find_inst[b * KF + 0], i1 = find_inst[b * KF + 1];
    for (int c = threadIdx.x; c < CC; c += blockDim.x) {
        w0[c] = W_find[(size_t)i0 * CC + c];
        w1[c] = W_find[(size_t)i1 * CC + c];
    }
    __syncthreads();
    float m = 0.f;
    int t = threadIdx.x;
    if (t < HW) {
        const float* fb = feat + (size_t)b * CC * HW + t;
        float a0 = 0.f, a1 = 0.f;
#pragma unroll 4
        for (int c = 0; c < CC; c++) {
            float f = fb[(size_t)c * HW];
            a0 = fmaf(w0[c], f, a0);
            a1 = fmaf(w1[c], f, a1);
        }
        a0 = fmaxf(a0, 0.f); a1 = fmaxf(a1, 0.f);
        m = a0 * a1;
        g_maps[b * HW + t] = m;
    }
    red[threadIdx.x] = m; __syncthreads();
    for (int s = 128; s > 0; s >>= 1) {
        if (threadIdx.x < s) red[threadIdx.x] += red[threadIdx.x + s];
        __syncthreads();
    }
    if (threadIdx.x == 0) g_denom[b] = red[0] + 1e-6f;
}

// ---- Describe attend: attended[b,c] = sum_hw (maps/denom)[hw] * feat[b,c,hw] ----
__global__ void attend_kernel(const float* __restrict__ feat) {
    int b = blockIdx.x;
    __shared__ float ms[HW];
    float inv = 1.f / g_denom[b];
    for (int t = threadIdx.x; t < HW; t += blockDim.x) ms[t] = g_maps[b * HW + t] * inv;
    __syncthreads();
    int c = threadIdx.x;  // blockDim = 512
    const float4* fb = (const float4*)(feat + (size_t)(b * CC + c) * HW);
    float acc = 0.f;
    for (int q = 0; q < HW / 4; q++) {
        float4 f = fb[q];
        acc = fmaf(ms[4 * q + 0], f.x, acc);
        acc = fmaf(ms[4 * q + 1], f.y, acc);
        acc = fmaf(ms[4 * q + 2], f.z, acc);
        acc = fmaf(ms[4 * q + 3], f.w, acc);
    }
    g_att[b * CC + c] = acc;
}

// ---- Measure hidden: h = relu(mflat @ W_meas1[r] + b_meas1[r]) (yes samples only) ----
// grid (2, BN): split m-dim across 2 blocks to raise active-block count.
__global__ void measure_kernel(const int* __restrict__ root,
                               const int* __restrict__ yes,
                               const float* __restrict__ W1,
                               const float* __restrict__ b1) {
    int b = blockIdx.y;
    if (yes[b] == 0) return;  // block-uniform
    __shared__ float mf[HW];
    for (int t = threadIdx.x; t < HW; t += blockDim.x) mf[t] = g_maps[b * HW + t];
    __syncthreads();
    int m = blockIdx.x * 256 + threadIdx.x;  // blockDim = 256
    int r = root[b];
    const float* W = W1 + (size_t)r * HW * MH + m;
    float acc = b1[r * MH + m];
#pragma unroll 4
    for (int i = 0; i < HW; i++) acc = fmaf(mf[i], W[(size_t)i * MH], acc);
    g_hmeas[b * MH + m] = fmaxf(acc, 0.f);
}

// ---- Root logits: yes -> h@W_meas2+b2 ; no -> attended@W_desc[r]+b_desc[r] ----
__global__ void rootlogits_kernel(const int* __restrict__ root,
                                  const int* __restrict__ yes,
                                  const float* __restrict__ Wm2,
                                  const float* __restrict__ bm2,
                                  const float* __restrict__ Wd,
                                  const float* __restrict__ bd) {
    int b = blockIdx.y;
    int a = blockIdx.x * blockDim.x + threadIdx.x;
    __shared__ float v[512];  // MH == CC == 512
    bool y = yes[b] != 0;
    int r = root[b];
    const float* src = y ? &g_hmeas[b * MH] : &g_att[b * CC];
    for (int i = threadIdx.x; i < 512; i += blockDim.x) v[i] = src[i];
    __syncthreads();
    if (a >= AA) return;
    const float* W = y ? (Wm2 + a) : (Wd + (size_t)r * CC * AA + a);
    float acc = y ? bm2[a] : bd[r * AA + a];
#pragma unroll 4
    for (int i = 0; i < 512; i++) acc = fmaf(v[i], W[(size_t)i * AA], acc);
    g_root[b * AA + a] = acc;
}

// ---- softmax over root logits (in place) ----
__global__ void softmax_root_kernel() {
    int b = blockIdx.x;
    __shared__ float red[256];
    int tid = threadIdx.x;
    float mx = -3.4e38f;
    for (int a = tid; a < AA; a += blockDim.x) mx = fmaxf(mx, g_root[b * AA + a]);
    red[tid] = mx; __syncthreads();
    for (int s = 128; s > 0; s >>= 1) { if (tid < s) red[tid] = fmaxf(red[tid], red[tid + s]); __syncthreads(); }
    mx = red[0]; __syncthreads();
    float sum = 0.f;
    for (int a = tid; a < AA; a += blockDim.x) {
        float e = expf(g_root[b * AA + a] - mx);
        g_root[b * AA + a] = e;
        sum += e;
    }
    red[tid] = sum; __syncthreads();
    for (int s = 128; s > 0; s >>= 1) { if (tid < s) red[tid] += red[tid + s]; __syncthreads(); }
    float inv = 1.f / red[0];
    for (int a = tid; a < AA; a += blockDim.x) g_root[b * AA + a] *= inv;
}

// ---- X = emb@Wx + b_lstm for all (b,t) rows: 2560 x 4096, K=300 ----
// Each thread computes 2 output columns (float2 weight loads) for 16 rows.
__global__ __launch_bounds__(128) void xw_kernel(const int* __restrict__ question,
                                                 const float* __restrict__ Eemb,
                                                 const float* __restrict__ Wx,
                                                 const float* __restrict__ b_lstm) {
    const int RT = 16;
    int tid = threadIdx.x;
    int n0 = blockIdx.x * 256 + tid * 2;      // grid.x = G4/256 = 16
    int r0 = blockIdx.y * RT;                 // grid.y = 160
    __shared__ __align__(16) float es[RT][EE];
    __shared__ int toks[RT];
    if (tid < RT) toks[tid] = question[r0 + tid];
    __syncthreads();
    for (int idx = tid; idx < RT * EE; idx += 128) {
        int rr = idx / EE, e = idx - rr * EE;
        es[rr][e] = Eemb[(size_t)toks[rr] * EE + e];
    }
    __syncthreads();
    float2 bias = *(const float2*)&b_lstm[n0];
    float accx[RT], accy[RT];
#pragma unroll
    for (int rr = 0; rr < RT; rr++) { accx[rr] = bias.x; accy[rr] = bias.y; }
    for (int e = 0; e < EE; e += 4) {   // EE = 300 = 4*75
        float2 w0 = *(const float2*)&Wx[(size_t)e * G4 + n0];
        float2 w1 = *(const float2*)&Wx[(size_t)(e + 1) * G4 + n0];
        float2 w2 = *(const float2*)&Wx[(size_t)(e + 2) * G4 + n0];
        float2 w3 = *(const float2*)&Wx[(size_t)(e + 3) * G4 + n0];
#pragma unroll
        for (int rr = 0; rr < RT; rr++) {
            float4 ev = *(const float4*)&es[rr][e];
            accx[rr] = fmaf(ev.x, w0.x, accx[rr]);
            accy[rr] = fmaf(ev.x, w0.y, accy[rr]);
            accx[rr] = fmaf(ev.y, w1.x, accx[rr]);
            accy[rr] = fmaf(ev.y, w1.y, accy[rr]);
            accx[rr] = fmaf(ev.z, w2.x, accx[rr]);
            accy[rr] = fmaf(ev.z, w2.y, accy[rr]);
            accx[rr] = fmaf(ev.w, w3.x, accx[rr]);
            accy[rr] = fmaf(ev.w, w3.y, accy[rr]);
        }
    }
#pragma unroll
    for (int rr = 0; rr < RT; rr++) {
        float2 o; o.x = accx[rr]; o.y = accy[rr];
        *(float2*)&g_X[(size_t)(r0 + rr) * G4 + n0] = o;
    }
}

// ---- Fused LSTM step: z = X[:,t,:] + h@Wh for ALL 4 gates of 128 j's,
//      then gate nonlinearities + c/h update in the epilogue.
//      Block = 8 batch rows x 128 j. Each (b,j) has a unique owner thread,
//      so c is updated in place and h[next]/hlast writes are race-free. ----
__global__ __launch_bounds__(128) void lstm_step_kernel(
    const float* __restrict__ Wh, const int* __restrict__ length,
    int t, int hsel) {
    const int BT = 8;
    __shared__ __align__(16) float hs[BT * LH];  // 32 KB
    int tid = threadIdx.x;
    int j = blockIdx.x * 128 + tid;              // grid.x = LH/128 = 8
    int b0 = blockIdx.y * BT;                    // grid.y = 16
    {
        const float4* src = (const float4*)&g_h[hsel][b0 * LH];
        float4* dst = (float4*)hs;
        for (int i = tid; i < BT * LH / 4; i += 128) dst[i] = src[i];
    }
    __syncthreads();

    float acc[BT][4];
#pragma unroll
    for (int bb = 0; bb < BT; bb++)
#pragma unroll
        for (int g = 0; g < 4; g++)
            acc[bb][g] = g_X[((size_t)(b0 + bb) * TT + t) * G4 + g * LH + j];

    const float* Wp = Wh + j;
    for (int k = 0; k < LH; k += 4) {
        float w[4][4];
#pragma unroll
        for (int kk = 0; kk < 4; kk++)
#pragma unroll
            for (int g = 0; g < 4; g++)
                w[kk][g] = Wp[(size_t)(k + kk) * G4 + g * LH];
#pragma unroll
        for (int bb = 0; bb < BT; bb++) {
            float4 hv = *(const float4*)&hs[bb * LH + k];  // warp-broadcast LDS
#pragma unroll
            for (int g = 0; g < 4; g++) {
                acc[bb][g] = fmaf(hv.x, w[0][g], acc[bb][g]);
                acc[bb][g] = fmaf(hv.y, w[1][g], acc[bb][g]);
                acc[bb][g] = fmaf(hv.z, w[2][g], acc[bb][g]);
                acc[bb][g] = fmaf(hv.w, w[3][g], acc[bb][g]);
            }
        }
    }

    int hnext = hsel ^ 1;
#pragma unroll
    for (int bb = 0; bb < BT; bb++) {
        int b = b0 + bb;
        float zi = acc[bb][0], zf = acc[bb][1], zg = acc[bb][2], zo = acc[bb][3];
        float cprev = g_c[b * LH + j];
        float ig = 1.f / (1.f + expf(-zi));
        float fg = 1.f / (1.f + expf(-zf));
        float og = 1.f / (1.f + expf(-zo));
        float c = fg * cprev + ig * tanhf(zg);
        float h = og * tanhf(c);
        g_c[b * LH + j] = c;
        g_h[hnext][b * LH + j] = h;
        if (length[b] - 1 == t) g_hlast[b * LH + j] = h;
    }
}

// ---- enc logits = h_last @ W_enc + b_enc : 128 x 2000, K=1024 ----
__global__ __launch_bounds__(128) void enc_kernel(const float* __restrict__ Wenc,
                                                  const float* __restrict__ benc) {
    const int BT = 8;
    __shared__ __align__(16) float hs[BT * LH];  // 32 KB
    int n = blockIdx.x * 128 + threadIdx.x;      // grid.x = 16
    int b0 = blockIdx.y * BT;                    // grid.y = 16
    {
        const float4* src = (const float4*)&g_hlast[b0 * LH];
        float4* dst = (float4*)hs;
        for (int i = threadIdx.x; i < BT * LH / 4; i += 128) dst[i] = src[i];
    }
    __syncthreads();
    if (n >= AA) return;
    float acc[BT];
    float bias = benc[n];
#pragma unroll
    for (int bb = 0; bb < BT; bb++) acc[bb] = bias;
    for (int k = 0; k < LH; k += 4) {
        float w0 = Wenc[(size_t)k * AA + n];
        float w1 = Wenc[(size_t)(k + 1) * AA + n];
        float w2 = Wenc[(size_t)(k + 2) * AA + n];
        float w3 = Wenc[(size_t)(k + 3) * AA + n];
#pragma unroll
        for (int bb = 0; bb < BT; bb++) {
            float4 hv = *(const float4*)&hs[bb * LH + k];
            acc[bb] = fmaf(hv.x, w0, acc[bb]);
            acc[bb] = fmaf(hv.y, w1, acc[bb]);
            acc[bb] = fmaf(hv.z, w2, acc[bb]);
            acc[bb] = fmaf(hv.w, w3, acc[bb]);
        }
    }
#pragma unroll
    for (int bb = 0; bb < BT; bb++) g_enc[(b0 + bb) * AA + n] = acc[bb];
}

// ---- final: softmax(enc) and out = sqrt(root_pred * enc_pred) ----
__global__ void final_kernel(float* __restrict__ out) {
    int b = blockIdx.x;
    __shared__ float red[256];
    int tid = threadIdx.x;
    float mx = -3.4e38f;
    for (int a = tid; a < AA; a += blockDim.x) mx = fmaxf(mx, g_enc[b * AA + a]);
    red[tid] = mx; __syncthreads();
    for (int s = 128; s > 0; s >>= 1) { if (tid < s) red[tid] = fmaxf(red[tid], red[tid + s]); __syncthreads(); }
    mx = red[0]; __syncthreads();
    float sum = 0.f;
    for (int a = tid; a < AA; a += blockDim.x) sum += expf(g_enc[b * AA + a] - mx);
    red[tid] = sum; __syncthreads();
    for (int s = 128; s > 0; s >>= 1) { if (tid < s) red[tid] += red[tid + s]; __syncthreads(); }
    float inv = 1.f / red[0];
    for (int a = tid; a < AA; a += blockDim.x) {
        float e = expf(g_enc[b * AA + a] - mx) * inv;
        out[b * AA + a] = sqrtf(g_root[b * AA + a] * e);
    }
}

extern "C" void kernel_launch(void* const* d_in, const int* in_sizes, int n_in,
                              void* d_out, int out_size) {
    const float* features        = (const float*)d_in[0];
    const int* question          = (const int*)d_in[1];
    const int* length            = (const int*)d_in[2];
    const int* yesno             = (const int*)d_in[3];   // bool upcast; nonzero test
    const int* root_inst         = (const int*)d_in[4];
    const int* find_inst         = (const int*)d_in[5];
    const float* W_find          = (const float*)d_in[6];
    const float* W_meas1         = (const float*)d_in[7];
    const float* b_meas1         = (const float*)d_in[8];
    const float* W_meas2         = (const float*)d_in[9];
    const float* b_meas2         = (const float*)d_in[10];
    const float* W_desc          = (const float*)d_in[11];
    const float* b_desc          = (const float*)d_in[12];
    const float* E_emb           = (const float*)d_in[13];
    const float* Wx              = (const float*)d_in[14];
    const float* Wh              = (const float*)d_in[15];
    const float* b_lstm          = (const float*)d_in[16];
    const float* W_enc           = (const float*)d_in[17];
    const float* b_enc           = (const float*)d_in[18];
    float* out = (float*)d_out;

    // init recurrent state
    zero_kernel<<<(BN * LH + 255) / 256, 256>>>();

    // module network
    find_kernel<<<BN, 256>>>(features, find_inst, W_find);
    attend_kernel<<<BN, 512>>>(features);
    measure_kernel<<<dim3(2, BN), 256>>>(root_inst, yesno, W_meas1, b_meas1);
    rootlogits_kernel<<<dim3(8, BN), 256>>>(root_inst, yesno, W_meas2, b_meas2, W_desc, b_desc);
    softmax_root_kernel<<<BN, 256>>>();

    // question encoder
    xw_kernel<<<dim3(G4 / 256, (BN * TT) / 16), 128>>>(question, E_emb, Wx, b_lstm);
    for (int t = 0; t < TT; t++) {
        lstm_step_kernel<<<dim3(LH / 128, BN / 8), 128>>>(Wh, length, t, t & 1);
    }
    enc_kernel<<<dim3((AA + 127) / 128, BN / 8), 128>>>(W_enc, b_enc);

    // blend
    final_kernel<<<BN, 256>>>(out);
}

// round 8
// speedup vs baseline: 1.3716x; 1.3716x over previous
#include <cuda_runtime.h>
#include <math.h>

// ---- problem dims ----
#define BN 128
#define CC 512
#define HW 196
#define KF 2
#define AA 2000
#define TT 20
#define EE 300
#define LH 1024
#define MH 512
#define G4 4096   // 4*LH

// ---- scratch (device globals; no runtime allocation) ----
__device__ float g_maps[BN * HW];
__device__ float g_denom[BN];
__device__ float g_hmeas[BN * MH];
__device__ float g_att[BN * CC];
__device__ float g_root[BN * AA];               // logits -> softmax probs (in place)
__device__ float g_X[(size_t)BN * TT * G4];     // emb@Wx + b_lstm, precomputed
__device__ float g_z[BN * G4];                  // per-step gate pre-activations
__device__ float g_h[2][BN * LH];               // double-buffered hidden state
__device__ float g_c[BN * LH];
__device__ float g_hlast[BN * LH];
__device__ float g_enc[BN * AA];

// ---- Find: maps[b,hw] = relu(w0.f) * relu(w1.f); denom[b] = sum + 1e-6 ----
__global__ void find_kernel(const float* __restrict__ feat,
                            const int* __restrict__ find_inst,
                            const float* __restrict__ W_find) {
    int b = blockIdx.x;
    __shared__ float w0[CC], w1[CC];
    __shared__ float red[256];
    int i0 = find_inst[b * KF + 0], i1 = find_inst[b * KF + 1];
    for (int c = threadIdx.x; c < CC; c += blockDim.x) {
        w0[c] = W_find[(size_t)i0 * CC + c];
        w1[c] = W_find[(size_t)i1 * CC + c];
    }
    __syncthreads();
    float m = 0.f;
    int t = threadIdx.x;
    if (t < HW) {
        const float* fb = feat + (size_t)b * CC * HW + t;
        float a0 = 0.f, a1 = 0.f;
#pragma unroll 4
        for (int c = 0; c < CC; c++) {
            float f = fb[(size_t)c * HW];
            a0 = fmaf(w0[c], f, a0);
            a1 = fmaf(w1[c], f, a1);
        }
        a0 = fmaxf(a0, 0.f); a1 = fmaxf(a1, 0.f);
        m = a0 * a1;
        g_maps[b * HW + t] = m;
    }
    red[threadIdx.x] = m; __syncthreads();
    for (int s = 128; s > 0; s >>= 1) {
        if (threadIdx.x < s) red[threadIdx.x] += red[threadIdx.x + s];
        __syncthreads();
    }
    if (threadIdx.x == 0) g_denom[b] = red[0] + 1e-6f;
}

// ---- Describe attend: attended[b,c] = sum_hw (maps/denom)[hw] * feat[b,c,hw] ----
__global__ void attend_kernel(const float* __restrict__ feat) {
    int b = blockIdx.x;
    __shared__ float ms[HW];
    float inv = 1.f / g_denom[b];
    for (int t = threadIdx.x; t < HW; t += blockDim.x) ms[t] = g_maps[b * HW + t] * inv;
    __syncthreads();
    int c = threadIdx.x;  // blockDim = 512
    const float4* fb = (const float4*)(feat + (size_t)(b * CC + c) * HW);
    float acc = 0.f;
    for (int q = 0; q < HW / 4; q++) {
        float4 f = fb[q];
        acc = fmaf(ms[4 * q + 0], f.x, acc);
        acc = fmaf(ms[4 * q + 1], f.y, acc);
        acc = fmaf(ms[4 * q + 2], f.z, acc);
        acc = fmaf(ms[4 * q + 3], f.w, acc);
    }
    g_att[b * CC + c] = acc;
}

// ---- Measure hidden: h = relu(mflat @ W_meas1[r] + b_meas1[r]) (yes samples only) ----
__global__ void measure_kernel(const int* __restrict__ root,
                               const int* __restrict__ yes,
                               const float* __restrict__ W1,
                               const float* __restrict__ b1) {
    int b = blockIdx.y;
    if (yes[b] == 0) return;  // block-uniform
    __shared__ float mf[HW];
    for (int t = threadIdx.x; t < HW; t += blockDim.x) mf[t] = g_maps[b * HW + t];
    __syncthreads();
    int m = blockIdx.x * 256 + threadIdx.x;  // blockDim = 256
    int r = root[b];
    const float* W = W1 + (size_t)r * HW * MH + m;
    float acc = b1[r * MH + m];
#pragma unroll 4
    for (int i = 0; i < HW; i++) acc = fmaf(mf[i], W[(size_t)i * MH], acc);
    g_hmeas[b * MH + m] = fmaxf(acc, 0.f);
}

// ---- Root logits: yes -> h@W_meas2+b2 ; no -> attended@W_desc[r]+b_desc[r] ----
__global__ void rootlogits_kernel(const int* __restrict__ root,
                                  const int* __restrict__ yes,
                                  const float* __restrict__ Wm2,
                                  const float* __restrict__ bm2,
                                  const float* __restrict__ Wd,
                                  const float* __restrict__ bd) {
    int b = blockIdx.y;
    int a = blockIdx.x * blockDim.x + threadIdx.x;
    __shared__ float v[512];  // MH == CC == 512
    bool y = yes[b] != 0;
    int r = root[b];
    const float* src = y ? &g_hmeas[b * MH] : &g_att[b * CC];
    for (int i = threadIdx.x; i < 512; i += blockDim.x) v[i] = src[i];
    __syncthreads();
    if (a >= AA) return;
    const float* W = y ? (Wm2 + a) : (Wd + (size_t)r * CC * AA + a);
    float acc = y ? bm2[a] : bd[r * AA + a];
#pragma unroll 4
    for (int i = 0; i < 512; i++) acc = fmaf(v[i], W[(size_t)i * AA], acc);
    g_root[b * AA + a] = acc;
}

// ---- softmax over root logits (in place) ----
__global__ void softmax_root_kernel() {
    int b = blockIdx.x;
    __shared__ float red[256];
    int tid = threadIdx.x;
    float mx = -3.4e38f;
    for (int a = tid; a < AA; a += blockDim.x) mx = fmaxf(mx, g_root[b * AA + a]);
    red[tid] = mx; __syncthreads();
    for (int s = 128; s > 0; s >>= 1) { if (tid < s) red[tid] = fmaxf(red[tid], red[tid + s]); __syncthreads(); }
    mx = red[0]; __syncthreads();
    float sum = 0.f;
    for (int a = tid; a < AA; a += blockDim.x) {
        float e = expf(g_root[b * AA + a] - mx);
        g_root[b * AA + a] = e;
        sum += e;
    }
    red[tid] = sum; __syncthreads();
    for (int s = 128; s > 0; s >>= 1) { if (tid < s) red[tid] += red[tid + s]; __syncthreads(); }
    float inv = 1.f / red[0];
    for (int a = tid; a < AA; a += blockDim.x) g_root[b * AA + a] *= inv;
}

// ---- X = emb@Wx + b_lstm for all (b,t) rows: 2560 x 4096, K=300 ----
__global__ __launch_bounds__(128) void xw_kernel(const int* __restrict__ question,
                                                 const float* __restrict__ Eemb,
                                                 const float* __restrict__ Wx,
                                                 const float* __restrict__ b_lstm) {
    const int RT = 16;
    int tid = threadIdx.x;
    int n0 = blockIdx.x * 256 + tid * 2;      // grid.x = G4/256 = 16
    int r0 = blockIdx.y * RT;                 // grid.y = 160
    __shared__ __align__(16) float es[RT][EE];
    __shared__ int toks[RT];
    if (tid < RT) toks[tid] = question[r0 + tid];
    __syncthreads();
    for (int idx = tid; idx < RT * EE; idx += 128) {
        int rr = idx / EE, e = idx - rr * EE;
        es[rr][e] = Eemb[(size_t)toks[rr] * EE + e];
    }
    __syncthreads();
    float2 bias = *(const float2*)&b_lstm[n0];
    float accx[RT], accy[RT];
#pragma unroll
    for (int rr = 0; rr < RT; rr++) { accx[rr] = bias.x; accy[rr] = bias.y; }
    for (int e = 0; e < EE; e += 4) {   // EE = 300 = 4*75
        float2 w0 = *(const float2*)&Wx[(size_t)e * G4 + n0];
        float2 w1 = *(const float2*)&Wx[(size_t)(e + 1) * G4 + n0];
        float2 w2 = *(const float2*)&Wx[(size_t)(e + 2) * G4 + n0];
        float2 w3 = *(const float2*)&Wx[(size_t)(e + 3) * G4 + n0];
#pragma unroll
        for (int rr = 0; rr < RT; rr++) {
            float4 ev = *(const float4*)&es[rr][e];
            accx[rr] = fmaf(ev.x, w0.x, accx[rr]);
            accy[rr] = fmaf(ev.x, w0.y, accy[rr]);
            accx[rr] = fmaf(ev.y, w1.x, accx[rr]);
            accy[rr] = fmaf(ev.y, w1.y, accy[rr]);
            accx[rr] = fmaf(ev.z, w2.x, accx[rr]);
            accy[rr] = fmaf(ev.z, w2.y, accy[rr]);
            accx[rr] = fmaf(ev.w, w3.x, accx[rr]);
            accy[rr] = fmaf(ev.w, w3.y, accy[rr]);
        }
    }
#pragma unroll
    for (int rr = 0; rr < RT; rr++) {
        float2 o; o.x = accx[rr]; o.y = accy[rr];
        *(float2*)&g_X[(size_t)(r0 + rr) * G4 + n0] = o;
    }
}

// ---- z = X[:,t,:] + h@Wh : 128 x 4096, K=1024 ----
// 512 blocks (13.8 warps/SM) + explicit double-buffered weight prefetch
// (k unrolled by 8, next chunk's 8 weights in flight during current FFMAs).
__global__ __launch_bounds__(128) void zgemm_kernel(const float* __restrict__ Wh,
                                                    int t, int hsel) {
    const int BT = 8;
    __shared__ __align__(16) float hs[BT * LH];  // 32 KB
    int tid = threadIdx.x;
    int n = blockIdx.x * 128 + tid;              // grid.x = 32
    int b0 = blockIdx.y * BT;                    // grid.y = 16
    {
        const float4* src = (const float4*)&g_h[hsel][b0 * LH];
        float4* dst = (float4*)hs;
        for (int i = tid; i < BT * LH / 4; i += 128) dst[i] = src[i];
    }

    const float* Wp = Wh + n;
    float wcur[8], wnxt[8];
#pragma unroll
    for (int kk = 0; kk < 8; kk++) wcur[kk] = Wp[(size_t)kk * G4];

    float acc[BT];
#pragma unroll
    for (int bb = 0; bb < BT; bb++)
        acc[bb] = g_X[((size_t)(b0 + bb) * TT + t) * G4 + n];

    __syncthreads();

    for (int k = 0; k < LH; k += 8) {
        if (k + 8 < LH) {
#pragma unroll
            for (int kk = 0; kk < 8; kk++) wnxt[kk] = Wp[(size_t)(k + 8 + kk) * G4];
        }
#pragma unroll
        for (int kk = 0; kk < 8; kk += 4) {
#pragma unroll
            for (int bb = 0; bb < BT; bb++) {
                float4 hv = *(const float4*)&hs[bb * LH + k + kk];  // warp-broadcast
                acc[bb] = fmaf(hv.x, wcur[kk + 0], acc[bb]);
                acc[bb] = fmaf(hv.y, wcur[kk + 1], acc[bb]);
                acc[bb] = fmaf(hv.z, wcur[kk + 2], acc[bb]);
                acc[bb] = fmaf(hv.w, wcur[kk + 3], acc[bb]);
            }
        }
#pragma unroll
        for (int kk = 0; kk < 8; kk++) wcur[kk] = wnxt[kk];
    }
#pragma unroll
    for (int bb = 0; bb < BT; bb++) g_z[(b0 + bb) * G4 + n] = acc[bb];
}

// ---- LSTM gate at t=0: h0 = 0, so z0 = X[:,0,:]; no GEMM needed ----
__global__ void gate0_kernel(const int* __restrict__ length) {
    int b = blockIdx.x;
    bool last = (length[b] == 1);
    const float* xb = &g_X[(size_t)b * TT * G4];
    for (int j = threadIdx.x; j < LH; j += blockDim.x) {
        float zi = xb[j];
        float zg = xb[j + 2 * LH];
        float zo = xb[j + 3 * LH];
        float ig = 1.f / (1.f + expf(-zi));
        float og = 1.f / (1.f + expf(-zo));
        float c = ig * tanhf(zg);           // cprev = 0 (forget term vanishes)
        float h = og * tanhf(c);
        g_c[b * LH + j] = c;
        g_h[1][b * LH + j] = h;
        if (last) g_hlast[b * LH + j] = h;
    }
}

// ---- LSTM gates: c,h update; capture h_last at t == length-1 ----
__global__ void gate_kernel(const int* __restrict__ length, int t, int hnext) {
    int b = blockIdx.x;
    bool last = (length[b] - 1) == t;
    for (int j = threadIdx.x; j < LH; j += blockDim.x) {
        float zi = g_z[b * G4 + j];
        float zf = g_z[b * G4 + j + LH];
        float zg = g_z[b * G4 + j + 2 * LH];
        float zo = g_z[b * G4 + j + 3 * LH];
        float cprev = g_c[b * LH + j];
        float ig = 1.f / (1.f + expf(-zi));
        float fg = 1.f / (1.f + expf(-zf));
        float og = 1.f / (1.f + expf(-zo));
        float c = fg * cprev + ig * tanhf(zg);
        float h = og * tanhf(c);
        g_c[b * LH + j] = c;
        g_h[hnext][b * LH + j] = h;
        if (last) g_hlast[b * LH + j] = h;
    }
}

// ---- enc logits = h_last @ W_enc + b_enc : 128 x 2000, K=1024 ----
__global__ __launch_bounds__(128) void enc_kernel(const float* __restrict__ Wenc,
                                                  const float* __restrict__ benc) {
    const int BT = 8;
    __shared__ __align__(16) float hs[BT * LH];  // 32 KB
    int n = blockIdx.x * 128 + threadIdx.x;      // grid.x = 16
    int b0 = blockIdx.y * BT;                    // grid.y = 16
    {
        const float4* src = (const float4*)&g_hlast[b0 * LH];
        float4* dst = (float4*)hs;
        for (int i = threadIdx.x; i < BT * LH / 4; i += 128) dst[i] = src[i];
    }
    __syncthreads();
    if (n >= AA) return;
    float acc[BT];
    float bias = benc[n];
#pragma unroll
    for (int bb = 0; bb < BT; bb++) acc[bb] = bias;
    for (int k = 0; k < LH; k += 4) {
        float w0 = Wenc[(size_t)k * AA + n];
        float w1 = Wenc[(size_t)(k + 1) * AA + n];
        float w2 = Wenc[(size_t)(k + 2) * AA + n];
        float w3 = Wenc[(size_t)(k + 3) * AA + n];
#pragma unroll
        for (int bb = 0; bb < BT; bb++) {
            float4 hv = *(const float4*)&hs[bb * LH + k];
            acc[bb] = fmaf(hv.x, w0, acc[bb]);
            acc[bb] = fmaf(hv.y, w1, acc[bb]);
            acc[bb] = fmaf(hv.z, w2, acc[bb]);
            acc[bb] = fmaf(hv.w, w3, acc[bb]);
        }
    }
#pragma unroll
    for (int bb = 0; bb < BT; bb++) g_enc[(b0 + bb) * AA + n] = acc[bb];
}

// ---- final: softmax(enc) and out = sqrt(root_pred * enc_pred) ----
__global__ void final_kernel(float* __restrict__ out) {
    int b = blockIdx.x;
    __shared__ float red[256];
    int tid = threadIdx.x;
    float mx = -3.4e38f;
    for (int a = tid; a < AA; a += blockDim.x) mx = fmaxf(mx, g_enc[b * AA + a]);
    red[tid] = mx; __syncthreads();
    for (int s = 128; s > 0; s >>= 1) { if (tid < s) red[tid] = fmaxf(red[tid], red[tid + s]); __syncthreads(); }
    mx = red[0]; __syncthreads();
    float sum = 0.f;
    for (int a = tid; a < AA; a += blockDim.x) sum += expf(g_enc[b * AA + a] - mx);
    red[tid] = sum; __syncthreads();
    for (int s = 128; s > 0; s >>= 1) { if (tid < s) red[tid] += red[tid + s]; __syncthreads(); }
    float inv = 1.f / red[0];
    for (int a = tid; a < AA; a += blockDim.x) {
        float e = expf(g_enc[b * AA + a] - mx) * inv;
        out[b * AA + a] = sqrtf(g_root[b * AA + a] * e);
    }
}

extern "C" void kernel_launch(void* const* d_in, const int* in_sizes, int n_in,
                              void* d_out, int out_size) {
    const float* features        = (const float*)d_in[0];
    const int* question          = (const int*)d_in[1];
    const int* length            = (const int*)d_in[2];
    const int* yesno             = (const int*)d_in[3];   // bool upcast; nonzero test
    const int* root_inst         = (const int*)d_in[4];
    const int* find_inst         = (const int*)d_in[5];
    const float* W_find          = (const float*)d_in[6];
    const float* W_meas1         = (const float*)d_in[7];
    const float* b_meas1         = (const float*)d_in[8];
    const float* W_meas2         = (const float*)d_in[9];
    const float* b_meas2         = (const float*)d_in[10];
    const float* W_desc          = (const float*)d_in[11];
    const float* b_desc          = (const float*)d_in[12];
    const float* E_emb           = (const float*)d_in[13];
    const float* Wx              = (const float*)d_in[14];
    const float* Wh              = (const float*)d_in[15];
    const float* b_lstm          = (const float*)d_in[16];
    const float* W_enc           = (const float*)d_in[17];
    const float* b_enc           = (const float*)d_in[18];
    float* out = (float*)d_out;

    // module network
    find_kernel<<<BN, 256>>>(features, find_inst, W_find);
    attend_kernel<<<BN, 512>>>(features);
    measure_kernel<<<dim3(2, BN), 256>>>(root_inst, yesno, W_meas1, b_meas1);
    rootlogits_kernel<<<dim3(8, BN), 256>>>(root_inst, yesno, W_meas2, b_meas2, W_desc, b_desc);
    softmax_root_kernel<<<BN, 256>>>();

    // question encoder
    xw_kernel<<<dim3(G4 / 256, (BN * TT) / 16), 128>>>(question, E_emb, Wx, b_lstm);
    gate0_kernel<<<BN, 256>>>(length);                       // t = 0: z = X, h0 = 0
    for (int t = 1; t < TT; t++) {
        zgemm_kernel<<<dim3(G4 / 128, BN / 8), 128>>>(Wh, t, t & 1);
        gate_kernel<<<BN, 256>>>(length, t, (t + 1) & 1);
    }
    enc_kernel<<<dim3((AA + 127) / 128, BN / 8), 128>>>(W_enc, b_enc);

    // blend
    final_kernel<<<BN, 256>>>(out);
}

// round 9
// speedup vs baseline: 1.9578x; 1.4275x over previous
#include <cuda_runtime.h>
#include <math.h>

// ---- problem dims ----
#define BN 128
#define CC 512
#define HW 196
#define KF 2
#define AA 2000
#define TT 20
#define EE 300
#define LH 1024
#define MH 512
#define G4 4096   // 4*LH
#define KSL 4     // K slices for zgemm
#define KS  (LH / KSL)  // 256

// ---- scratch (device globals; no runtime allocation) ----
__device__ float g_maps[BN * HW];
__device__ float g_denom[BN];
__device__ float g_hmeas[BN * MH];
__device__ float g_att[BN * CC];
__device__ float g_root[BN * AA];               // logits -> softmax probs (in place)
__device__ float g_X[(size_t)BN * TT * G4];     // emb@Wx + b_lstm, precomputed
__device__ float g_zp[KSL][BN * G4];            // per-K-slice gate partials
__device__ float g_h[2][BN * LH];               // double-buffered hidden state
__device__ float g_c[BN * LH];
__device__ float g_hlast[BN * LH];
__device__ float g_enc[BN * AA];

// ---- Find: maps[b,hw] = relu(w0.f) * relu(w1.f); denom[b] = sum + 1e-6 ----
__global__ void find_kernel(const float* __restrict__ feat,
                            const int* __restrict__ find_inst,
                            const float* __restrict__ W_find) {
    int b = blockIdx.x;
    __shared__ float w0[CC], w1[CC];
    __shared__ float red[256];
    int i0 = find_inst[b * KF + 0], i1 = find_inst[b * KF + 1];
    for (int c = threadIdx.x; c < CC; c += blockDim.x) {
        w0[c] = W_find[(size_t)i0 * CC + c];
        w1[c] = W_find[(size_t)i1 * CC + c];
    }
    __syncthreads();
    float m = 0.f;
    int t = threadIdx.x;
    if (t < HW) {
        const float* fb = feat + (size_t)b * CC * HW + t;
        float a0 = 0.f, a1 = 0.f;
#pragma unroll 4
        for (int c = 0; c < CC; c++) {
            float f = fb[(size_t)c * HW];
            a0 = fmaf(w0[c], f, a0);
            a1 = fmaf(w1[c], f, a1);
        }
        a0 = fmaxf(a0, 0.f); a1 = fmaxf(a1, 0.f);
        m = a0 * a1;
        g_maps[b * HW + t] = m;
    }
    red[threadIdx.x] = m; __syncthreads();
    for (int s = 128; s > 0; s >>= 1) {
        if (threadIdx.x < s) red[threadIdx.x] += red[threadIdx.x + s];
        __syncthreads();
    }
    if (threadIdx.x == 0) g_denom[b] = red[0] + 1e-6f;
}

// ---- Describe attend: attended[b,c] = sum_hw (maps/denom)[hw] * feat[b,c,hw] ----
__global__ void attend_kernel(const float* __restrict__ feat) {
    int b = blockIdx.x;
    __shared__ float ms[HW];
    float inv = 1.f / g_denom[b];
    for (int t = threadIdx.x; t < HW; t += blockDim.x) ms[t] = g_maps[b * HW + t] * inv;
    __syncthreads();
    int c = threadIdx.x;  // blockDim = 512
    const float4* fb = (const float4*)(feat + (size_t)(b * CC + c) * HW);
    float acc = 0.f;
    for (int q = 0; q < HW / 4; q++) {
        float4 f = fb[q];
        acc = fmaf(ms[4 * q + 0], f.x, acc);
        acc = fmaf(ms[4 * q + 1], f.y, acc);
        acc = fmaf(ms[4 * q + 2], f.z, acc);
        acc = fmaf(ms[4 * q + 3], f.w, acc);
    }
    g_att[b * CC + c] = acc;
}

// ---- Measure hidden: h = relu(mflat @ W_meas1[r] + b_meas1[r]) (yes samples only) ----
__global__ void measure_kernel(const int* __restrict__ root,
                               const int* __restrict__ yes,
                               const float* __restrict__ W1,
                               const float* __restrict__ b1) {
    int b = blockIdx.y;
    if (yes[b] == 0) return;  // block-uniform
    __shared__ float mf[HW];
    for (int t = threadIdx.x; t < HW; t += blockDim.x) mf[t] = g_maps[b * HW + t];
    __syncthreads();
    int m = blockIdx.x * 256 + threadIdx.x;  // blockDim = 256
    int r = root[b];
    const float* W = W1 + (size_t)r * HW * MH + m;
    float acc = b1[r * MH + m];
#pragma unroll 4
    for (int i = 0; i < HW; i++) acc = fmaf(mf[i], W[(size_t)i * MH], acc);
    g_hmeas[b * MH + m] = fmaxf(acc, 0.f);
}

// ---- Root logits: yes -> h@W_meas2+b2 ; no -> attended@W_desc[r]+b_desc[r] ----
__global__ void rootlogits_kernel(const int* __restrict__ root,
                                  const int* __restrict__ yes,
                                  const float* __restrict__ Wm2,
                                  const float* __restrict__ bm2,
                                  const float* __restrict__ Wd,
                                  const float* __restrict__ bd) {
    int b = blockIdx.y;
    int a = blockIdx.x * blockDim.x + threadIdx.x;
    __shared__ float v[512];  // MH == CC == 512
    bool y = yes[b] != 0;
    int r = root[b];
    const float* src = y ? &g_hmeas[b * MH] : &g_att[b * CC];
    for (int i = threadIdx.x; i < 512; i += blockDim.x) v[i] = src[i];
    __syncthreads();
    if (a >= AA) return;
    const float* W = y ? (Wm2 + a) : (Wd + (size_t)r * CC * AA + a);
    float acc = y ? bm2[a] : bd[r * AA + a];
#pragma unroll 4
    for (int i = 0; i < 512; i++) acc = fmaf(v[i], W[(size_t)i * AA], acc);
    g_root[b * AA + a] = acc;
}

// ---- softmax over root logits (in place) ----
__global__ void softmax_root_kernel() {
    int b = blockIdx.x;
    __shared__ float red[256];
    int tid = threadIdx.x;
    float mx = -3.4e38f;
    for (int a = tid; a < AA; a += blockDim.x) mx = fmaxf(mx, g_root[b * AA + a]);
    red[tid] = mx; __syncthreads();
    for (int s = 128; s > 0; s >>= 1) { if (tid < s) red[tid] = fmaxf(red[tid], red[tid + s]); __syncthreads(); }
    mx = red[0]; __syncthreads();
    float sum = 0.f;
    for (int a = tid; a < AA; a += blockDim.x) {
        float e = expf(g_root[b * AA + a] - mx);
        g_root[b * AA + a] = e;
        sum += e;
    }
    red[tid] = sum; __syncthreads();
    for (int s = 128; s > 0; s >>= 1) { if (tid < s) red[tid] += red[tid + s]; __syncthreads(); }
    float inv = 1.f / red[0];
    for (int a = tid; a < AA; a += blockDim.x) g_root[b * AA + a] *= inv;
}

// ---- X = emb@Wx + b_lstm for all (b,t) rows: 2560 x 4096, K=300 ----
__global__ __launch_bounds__(128) void xw_kernel(const int* __restrict__ question,
                                                 const float* __restrict__ Eemb,
                                                 const float* __restrict__ Wx,
                                                 const float* __restrict__ b_lstm) {
    const int RT = 16;
    int tid = threadIdx.x;
    int n0 = blockIdx.x * 256 + tid * 2;      // grid.x = G4/256 = 16
    int r0 = blockIdx.y * RT;                 // grid.y = 160
    __shared__ __align__(16) float es[RT][EE];
    __shared__ int toks[RT];
    if (tid < RT) toks[tid] = question[r0 + tid];
    __syncthreads();
    for (int idx = tid; idx < RT * EE; idx += 128) {
        int rr = idx / EE, e = idx - rr * EE;
        es[rr][e] = Eemb[(size_t)toks[rr] * EE + e];
    }
    __syncthreads();
    float2 bias = *(const float2*)&b_lstm[n0];
    float accx[RT], accy[RT];
#pragma unroll
    for (int rr = 0; rr < RT; rr++) { accx[rr] = bias.x; accy[rr] = bias.y; }
    for (int e = 0; e < EE; e += 4) {   // EE = 300 = 4*75
        float2 w0 = *(const float2*)&Wx[(size_t)e * G4 + n0];
        float2 w1 = *(const float2*)&Wx[(size_t)(e + 1) * G4 + n0];
        float2 w2 = *(const float2*)&Wx[(size_t)(e + 2) * G4 + n0];
        float2 w3 = *(const float2*)&Wx[(size_t)(e + 3) * G4 + n0];
#pragma unroll
        for (int rr = 0; rr < RT; rr++) {
            float4 ev = *(const float4*)&es[rr][e];
            accx[rr] = fmaf(ev.x, w0.x, accx[rr]);
            accy[rr] = fmaf(ev.x, w0.y, accy[rr]);
            accx[rr] = fmaf(ev.y, w1.x, accx[rr]);
            accy[rr] = fmaf(ev.y, w1.y, accy[rr]);
            accx[rr] = fmaf(ev.z, w2.x, accx[rr]);
            accy[rr] = fmaf(ev.z, w2.y, accy[rr]);
            accx[rr] = fmaf(ev.w, w3.x, accx[rr]);
            accy[rr] = fmaf(ev.w, w3.y, accy[rr]);
        }
    }
#pragma unroll
    for (int rr = 0; rr < RT; rr++) {
        float2 o; o.x = accx[rr]; o.y = accy[rr];
        *(float2*)&g_X[(size_t)(r0 + rr) * G4 + n0] = o;
    }
}

// ---- zgemm v3: partial z over one K slice. grid (16,16,4), 128 thr.
//      2 output cols/thread (float2 weights), BT=8 rows, 4k chunk prefetch.
//      slice 0 seeds with X (bias + emb term); others start at 0. ----
__global__ __launch_bounds__(128, 8) void zgemm_kernel(const float* __restrict__ Wh,
                                                       int t, int hsel) {
    const int BT = 8;
    __shared__ __align__(16) float hs[BT * KS];  // 8 KB
    int tid = threadIdx.x;
    int n0 = blockIdx.x * 256 + tid * 2;         // grid.x = 16
    int b0 = blockIdx.y * BT;                    // grid.y = 16
    int ks = blockIdx.z * KS;                    // grid.z = 4

    for (int i = tid; i < BT * KS / 4; i += 128) {
        int bb = i >> 6;                          // KS/4 = 64
        int q  = i & 63;
        *(float4*)&hs[bb * KS + q * 4] =
            *(const float4*)&g_h[hsel][(size_t)(b0 + bb) * LH + ks + q * 4];
    }

    const float* Wp = Wh + (size_t)ks * G4 + n0;
    float2 wcur[4], wnxt[4];
#pragma unroll
    for (int kk = 0; kk < 4; kk++) wcur[kk] = *(const float2*)&Wp[(size_t)kk * G4];

    float2 acc[BT];
    if (blockIdx.z == 0) {
#pragma unroll
        for (int bb = 0; bb < BT; bb++)
            acc[bb] = *(const float2*)&g_X[((size_t)(b0 + bb) * TT + t) * G4 + n0];
    } else {
#pragma unroll
        for (int bb = 0; bb < BT; bb++) { acc[bb].x = 0.f; acc[bb].y = 0.f; }
    }
    __syncthreads();

    for (int k = 0; k < KS; k += 4) {
        if (k + 4 < KS) {
#pragma unroll
            for (int kk = 0; kk < 4; kk++)
                wnxt[kk] = *(const float2*)&Wp[(size_t)(k + 4 + kk) * G4];
        }
#pragma unroll
        for (int bb = 0; bb < BT; bb++) {
            float4 hv = *(const float4*)&hs[bb * KS + k];  // warp-broadcast
            acc[bb].x = fmaf(hv.x, wcur[0].x, acc[bb].x);
            acc[bb].y = fmaf(hv.x, wcur[0].y, acc[bb].y);
            acc[bb].x = fmaf(hv.y, wcur[1].x, acc[bb].x);
            acc[bb].y = fmaf(hv.y, wcur[1].y, acc[bb].y);
            acc[bb].x = fmaf(hv.z, wcur[2].x, acc[bb].x);
            acc[bb].y = fmaf(hv.z, wcur[2].y, acc[bb].y);
            acc[bb].x = fmaf(hv.w, wcur[3].x, acc[bb].x);
            acc[bb].y = fmaf(hv.w, wcur[3].y, acc[bb].y);
        }
#pragma unroll
        for (int kk = 0; kk < 4; kk++) wcur[kk] = wnxt[kk];
    }
#pragma unroll
    for (int bb = 0; bb < BT; bb++)
        *(float2*)&g_zp[blockIdx.z][(size_t)(b0 + bb) * G4 + n0] = acc[bb];
}

// ---- LSTM gate at t=0: h0 = 0, so z0 = X[:,0,:]; no GEMM needed ----
__global__ void gate0_kernel(const int* __restrict__ length) {
    int b = blockIdx.x;
    bool last = (length[b] == 1);
    const float* xb = &g_X[(size_t)b * TT * G4];
    for (int j = threadIdx.x; j < LH; j += blockDim.x) {
        float zi = xb[j];
        float zg = xb[j + 2 * LH];
        float zo = xb[j + 3 * LH];
        float ig = 1.f / (1.f + expf(-zi));
        float og = 1.f / (1.f + expf(-zo));
        float c = ig * tanhf(zg);           // cprev = 0
        float h = og * tanhf(c);
        g_c[b * LH + j] = c;
        g_h[1][b * LH + j] = h;
        if (last) g_hlast[b * LH + j] = h;
    }
}

// ---- LSTM gates: sum 4 K-slice partials (fixed order), update c/h ----
__global__ void gate_kernel(const int* __restrict__ length, int t, int hnext) {
    int b = blockIdx.x;
    int j = threadIdx.x * 4;   // 256 threads -> 1024 j, 4 per thread
    bool last = (length[b] - 1) == t;
    float4 z[4];
#pragma unroll
    for (int g = 0; g < 4; g++) {
        size_t idx = (size_t)b * G4 + g * LH + j;
        float4 s0 = *(const float4*)&g_zp[0][idx];
        float4 s1 = *(const float4*)&g_zp[1][idx];
        float4 s2 = *(const float4*)&g_zp[2][idx];
        float4 s3 = *(const float4*)&g_zp[3][idx];
        z[g].x = s0.x + s1.x + s2.x + s3.x;
        z[g].y = s0.y + s1.y + s2.y + s3.y;
        z[g].z = s0.z + s1.z + s2.z + s3.z;
        z[g].w = s0.w + s1.w + s2.w + s3.w;
    }
    float4 cprev = *(const float4*)&g_c[b * LH + j];
    float4 cout, hout;
    {
        float zi[4] = {z[0].x, z[0].y, z[0].z, z[0].w};
        float zf[4] = {z[1].x, z[1].y, z[1].z, z[1].w};
        float zg[4] = {z[2].x, z[2].y, z[2].z, z[2].w};
        float zo[4] = {z[3].x, z[3].y, z[3].z, z[3].w};
        float cp[4] = {cprev.x, cprev.y, cprev.z, cprev.w};
        float co[4], ho[4];
#pragma unroll
        for (int l = 0; l < 4; l++) {
            float ig = 1.f / (1.f + expf(-zi[l]));
            float fg = 1.f / (1.f + expf(-zf[l]));
            float og = 1.f / (1.f + expf(-zo[l]));
            float c = fg * cp[l] + ig * tanhf(zg[l]);
            co[l] = c;
            ho[l] = og * tanhf(c);
        }
        cout.x = co[0]; cout.y = co[1]; cout.z = co[2]; cout.w = co[3];
        hout.x = ho[0]; hout.y = ho[1]; hout.z = ho[2]; hout.w = ho[3];
    }
    *(float4*)&g_c[b * LH + j] = cout;
    *(float4*)&g_h[hnext][b * LH + j] = hout;
    if (last) *(float4*)&g_hlast[b * LH + j] = hout;
}

// ---- enc logits = h_last @ W_enc + b_enc : 128 x 2000, K=1024 ----
__global__ __launch_bounds__(128) void enc_kernel(const float* __restrict__ Wenc,
                                                  const float* __restrict__ benc) {
    const int BT = 8;
    __shared__ __align__(16) float hs[BT * LH];  // 32 KB
    int n = blockIdx.x * 128 + threadIdx.x;      // grid.x = 16
    int b0 = blockIdx.y * BT;                    // grid.y = 16
    {
        const float4* src = (const float4*)&g_hlast[b0 * LH];
        float4* dst = (float4*)hs;
        for (int i = threadIdx.x; i < BT * LH / 4; i += 128) dst[i] = src[i];
    }
    __syncthreads();
    if (n >= AA) return;
    float acc[BT];
    float bias = benc[n];
#pragma unroll
    for (int bb = 0; bb < BT; bb++) acc[bb] = bias;
    for (int k = 0; k < LH; k += 4) {
        float w0 = Wenc[(size_t)k * AA + n];
        float w1 = Wenc[(size_t)(k + 1) * AA + n];
        float w2 = Wenc[(size_t)(k + 2) * AA + n];
        float w3 = Wenc[(size_t)(k + 3) * AA + n];
#pragma unroll
        for (int bb = 0; bb < BT; bb++) {
            float4 hv = *(const float4*)&hs[bb * LH + k];
            acc[bb] = fmaf(hv.x, w0, acc[bb]);
            acc[bb] = fmaf(hv.y, w1, acc[bb]);
            acc[bb] = fmaf(hv.z, w2, acc[bb]);
            acc[bb] = fmaf(hv.w, w3, acc[bb]);
        }
    }
#pragma unroll
    for (int bb = 0; bb < BT; bb++) g_enc[(b0 + bb) * AA + n] = acc[bb];
}

// ---- final: softmax(enc) and out = sqrt(root_pred * enc_pred) ----
__global__ void final_kernel(float* __restrict__ out) {
    int b = blockIdx.x;
    __shared__ float red[256];
    int tid = threadIdx.x;
    float mx = -3.4e38f;
    for (int a = tid; a < AA; a += blockDim.x) mx = fmaxf(mx, g_enc[b * AA + a]);
    red[tid] = mx; __syncthreads();
    for (int s = 128; s > 0; s >>= 1) { if (tid < s) red[tid] = fmaxf(red[tid], red[tid + s]); __syncthreads(); }
    mx = red[0]; __syncthreads();
    float sum = 0.f;
    for (int a = tid; a < AA; a += blockDim.x) sum += expf(g_enc[b * AA + a] - mx);
    red[tid] = sum; __syncthreads();
    for (int s = 128; s > 0; s >>= 1) { if (tid < s) red[tid] += red[tid + s]; __syncthreads(); }
    float inv = 1.f / red[0];
    for (int a = tid; a < AA; a += blockDim.x) {
        float e = expf(g_enc[b * AA + a] - mx) * inv;
        out[b * AA + a] = sqrtf(g_root[b * AA + a] * e);
    }
}

extern "C" void kernel_launch(void* const* d_in, const int* in_sizes, int n_in,
                              void* d_out, int out_size) {
    const float* features        = (const float*)d_in[0];
    const int* question          = (const int*)d_in[1];
    const int* length            = (const int*)d_in[2];
    const int* yesno             = (const int*)d_in[3];   // bool upcast; nonzero test
    const int* root_inst         = (const int*)d_in[4];
    const int* find_inst         = (const int*)d_in[5];
    const float* W_find          = (const float*)d_in[6];
    const float* W_meas1         = (const float*)d_in[7];
    const float* b_meas1         = (const float*)d_in[8];
    const float* W_meas2         = (const float*)d_in[9];
    const float* b_meas2         = (const float*)d_in[10];
    const float* W_desc          = (const float*)d_in[11];
    const float* b_desc          = (const float*)d_in[12];
    const float* E_emb           = (const float*)d_in[13];
    const float* Wx              = (const float*)d_in[14];
    const float* Wh              = (const float*)d_in[15];
    const float* b_lstm          = (const float*)d_in[16];
    const float* W_enc           = (const float*)d_in[17];
    const float* b_enc           = (const float*)d_in[18];
    float* out = (float*)d_out;

    // Side stream + fork/join events for overlapping the module network with
    // the encoder path. Created once (resources only; the launched work is
    // identical on every call, so determinism and graph capture are preserved).
    static cudaStream_t s_mod = nullptr;
    static cudaEvent_t ev_fork = nullptr, ev_join = nullptr;
    if (s_mod == nullptr) {
        cudaStreamCreateWithFlags(&s_mod, cudaStreamNonBlocking);
        cudaEventCreateWithFlags(&ev_fork, cudaEventDisableTiming);
        cudaEventCreateWithFlags(&ev_join, cudaEventDisableTiming);
    }

    // fork: module network on s_mod
    cudaEventRecord(ev_fork, 0);
    cudaStreamWaitEvent(s_mod, ev_fork, 0);
    find_kernel<<<BN, 256, 0, s_mod>>>(features, find_inst, W_find);
    attend_kernel<<<BN, 512, 0, s_mod>>>(features);
    measure_kernel<<<dim3(2, BN), 256, 0, s_mod>>>(root_inst, yesno, W_meas1, b_meas1);
    rootlogits_kernel<<<dim3(8, BN), 256, 0, s_mod>>>(root_inst, yesno, W_meas2, b_meas2, W_desc, b_desc);
    softmax_root_kernel<<<BN, 256, 0, s_mod>>>();
    cudaEventRecord(ev_join, s_mod);

    // main stream: question encoder
    xw_kernel<<<dim3(G4 / 256, (BN * TT) / 16), 128>>>(question, E_emb, Wx, b_lstm);
    gate0_kernel<<<BN, 256>>>(length);                       // t = 0: z = X, h0 = 0
    for (int t = 1; t < TT; t++) {
        zgemm_kernel<<<dim3(G4 / 256, BN / 8, KSL), 128>>>(Wh, t, t & 1);
        gate_kernel<<<BN, 256>>>(length, t, (t + 1) & 1);
    }
    enc_kernel<<<dim3((AA + 127) / 128, BN / 8), 128>>>(W_enc, b_enc);

    // join: final blend needs g_root from the module-network stream
    cudaStreamWaitEvent(0, ev_join, 0);
    final_kernel<<<BN, 256>>>(out);
}